// round 5
// baseline (speedup 1.0000x reference)
#include <cuda_runtime.h>
#include <math.h>

#define Dm      128
#define BATCH   65536
#define NROWS   500000
#define TSLOTS  3
#define SWW     132

#define AS_FLOATS   (128 * 128)
#define SMEM_FLOATS (AS_FLOATS * 2 + 128 * SWW)
#define SMEM_BYTES  (SMEM_FLOATS * 4 + 512)

#define PER_T4   (NROWS * 32)     // float4 per history slot = 16e6
#define TOTAL4   (3 * PER_T4)     // 48e6
#define NCTA     512
#define NCOPYT   64               // copy threads per CTA (2 warps)

__device__ int g_winner[NROWS];

// named barrier over the 8 compute warps only
#define BSYNC() asm volatile("bar.sync 1, 256;" ::: "memory")

// ---------------- helpers ----------------

// transposed activation layout: element (feature k, row r) at k*128 + (r XOR-swizzled)
__device__ __forceinline__ int aoff(int k, int r) {
    return k * 128 + (r ^ (((k >> 3) & 15) << 3));
}

__device__ __forceinline__ unsigned long long pk2(float v) {
    unsigned long long r;
    asm("mov.b64 %0, {%1, %1};" : "=l"(r) : "f"(v));
    return r;
}
__device__ __forceinline__ void ffma2(unsigned long long& d,
                                      unsigned long long a,
                                      unsigned long long b) {
    asm("fma.rn.f32x2 %0, %1, %2, %0;" : "+l"(d) : "l"(a), "l"(b));
}
__device__ __forceinline__ float2 upk(unsigned long long v) {
    float2 f;
    asm("mov.b64 {%0, %1}, %2;" : "=f"(f.x), "=f"(f.y) : "l"(v));
    return f;
}
__device__ __forceinline__ float sigf(float x) { return 1.0f / (1.0f + expf(-x)); }

// stage W tile: Ws[k][c] = Wg[c*128 + k]   (Wg row-major [out_c][in_k])
__device__ __forceinline__ void stage_W(float* __restrict__ Ws,
                                        const float* __restrict__ Wg, int tid) {
    const float4* W4 = (const float4*)Wg;
#pragma unroll
    for (int m = 0; m < 16; m++) {
        int f4 = tid + m * 256;      // float4 index over 4096
        int c  = f4 >> 5;            // 32 float4 per row of 128
        int kq = f4 & 31;
        float4 v = W4[f4];           // == Wg[c][4*kq .. 4*kq+3], coalesced
        int kk = kq * 4;
        Ws[(kk + 0) * SWW + c] = v.x;
        Ws[(kk + 1) * SWW + c] = v.y;
        Ws[(kk + 2) * SWW + c] = v.z;
        Ws[(kk + 3) * SWW + c] = v.w;
    }
}

// acc[r_i][c_pair] += A^T[k][r0+i] * Ws[k][c0+j]; acc packed as f32x2 col pairs
__device__ __forceinline__ void gemm_acc(const float* __restrict__ A,
                                         const float* __restrict__ Ws,
                                         unsigned long long acc[32],
                                         int r0, int c0) {
#pragma unroll 4
    for (int k = 0; k < 128; k++) {
        int sw = ((k >> 3) & 15) << 3;
        const float* abase = A + k * 128 + (r0 ^ sw);
        float4 a0 = *(const float4*)(abase);
        float4 a1 = *(const float4*)(abase + 4);
        const ulonglong2* wrow = (const ulonglong2*)(Ws + k * SWW + c0);
        ulonglong2 w01 = wrow[0];   // .x = cols(c0,c0+1) .y = cols(c0+2,c0+3)
        ulonglong2 w23 = wrow[1];
        unsigned long long ap[8];
        ap[0] = pk2(a0.x); ap[1] = pk2(a0.y); ap[2] = pk2(a0.z); ap[3] = pk2(a0.w);
        ap[4] = pk2(a1.x); ap[5] = pk2(a1.y); ap[6] = pk2(a1.z); ap[7] = pk2(a1.w);
#pragma unroll
        for (int i = 0; i < 8; i++) {
            ffma2(acc[i * 4 + 0], ap[i], w01.x);
            ffma2(acc[i * 4 + 1], ap[i], w01.y);
            ffma2(acc[i * 4 + 2], ap[i], w23.x);
            ffma2(acc[i * 4 + 3], ap[i], w23.y);
        }
    }
}

#define ZERO_ACC                                            \
    _Pragma("unroll") for (int zz = 0; zz < 32; zz++) acc[zz] = 0ULL;

// ---------------- winner kernels ----------------

__global__ void k_winit() {
    int i = blockIdx.x * blockDim.x + threadIdx.x;
    if (i < NROWS) g_winner[i] = -1;
}

__global__ void k_wscatter(const int* __restrict__ idx) {
    int b = blockIdx.x * blockDim.x + threadIdx.x;
    if (b < BATCH) atomicMax(&g_winner[idx[b]], b);
}

// ---------------- fused compute + warp-specialized history copy ----------------

__global__ void __launch_bounds__(256 + NCOPYT, 1) k_compute(
    const float* __restrict__ x, const int* __restrict__ idx,
    const float* __restrict__ hist,
    const float* __restrict__ W1, const float* __restrict__ b1,
    const float* __restrict__ W2, const float* __restrict__ b2,
    const float* __restrict__ W_ih, const float* __restrict__ b_ih,
    const float* __restrict__ W_hh, const float* __restrict__ b_hh,
    float* __restrict__ out, float* __restrict__ memout,
    float* __restrict__ nh)
{
    extern __shared__ float sm[];
    float* As = sm;                  // xf / activations, transposed [k][r]
    float* Ms = sm + AS_FLOATS;      // mem, transposed [k][r]
    float* Ws = sm + 2 * AS_FLOATS;  // weight tile [k][c], stride SWW
    int*   sIdx = (int*)(sm + SMEM_FLOATS);  // idx cache for this tile

    const int tid = threadIdx.x;

    // ======== COPY ROLE: threads 256..319 stream the history shift ========
    if (tid >= 256) {
        const float4* hist4 = (const float4*)hist;
        float4* nh4 = (float4*)nh;
        const long long stride = (long long)NCTA * NCOPYT;   // 32768
        long long id = (long long)blockIdx.x * NCOPYT + (tid - 256);
#pragma unroll 4
        for (; id < (long long)TOTAL4; id += stride) {
            int t   = (int)(id / PER_T4);
            int rem = (int)(id - (long long)t * PER_T4);
            int w = __ldg(&g_winner[rem >> 5]);
            if (t < 2) {
                nh4[id] = hist4[(long long)(t + (w >= 0 ? 1 : 0)) * PER_T4 + rem];
            } else if (w < 0) {
                nh4[id] = hist4[id];
            }
        }
        return;
    }

    // ======== COMPUTE ROLE: threads 0..255 ========
    const int tx  = tid & 15;
    const int ty  = tid >> 4;
    const int r0  = ty * 8;
    const int c0  = tx * 8;
    const long long rowbase = (long long)blockIdx.x * 128;

    // ---- load x tile and gather mem tile (transposed into smem), write mem out ----
    {
        int row  = tid >> 1;
        int half = tid & 1;
        const float4* xr = (const float4*)(x + (rowbase + row) * Dm) + half * 16;
        int gi = idx[rowbase + row];
        if (half == 0) sIdx[row] = gi;
        const float4* mr =
            (const float4*)(hist + ((long long)(TSLOTS - 1) * NROWS + gi) * Dm) + half * 16;
        float4* mo = (float4*)(memout + (rowbase + row) * Dm) + half * 16;
#pragma unroll
        for (int m = 0; m < 16; m++) {
            float4 vx = xr[m];
            float4 vm = mr[m];
            mo[m] = vm;
            int k = half * 64 + m * 4;
            As[aoff(k + 0, row)] = vx.x;
            As[aoff(k + 1, row)] = vx.y;
            As[aoff(k + 2, row)] = vx.z;
            As[aoff(k + 3, row)] = vx.w;
            Ms[aoff(k + 0, row)] = vm.x;
            Ms[aoff(k + 1, row)] = vm.y;
            Ms[aoff(k + 2, row)] = vm.z;
            Ms[aoff(k + 3, row)] = vm.w;
        }
    }

    unsigned long long acc[32];
    float hold[8][8];   // r -> r*ghn -> n
    float v[8][8];      // scratch

    // ===== GEMM 1: h1 = elu(x@W1^T + b1) =====
    stage_W(Ws, W1, tid);
    BSYNC();
    ZERO_ACC;
    gemm_acc(As, Ws, acc, r0, c0);
    BSYNC();   // all reads of As/Ws done
    {
        float bb[8];
#pragma unroll
        for (int j = 0; j < 8; j++) bb[j] = b1[c0 + j];
#pragma unroll
        for (int i = 0; i < 8; i++)
#pragma unroll
            for (int j2 = 0; j2 < 4; j2++) {
                float2 p = upk(acc[i * 4 + j2]);
                float a = p.x + bb[2 * j2];
                float b = p.y + bb[2 * j2 + 1];
                v[i][2 * j2]     = (a > 0.f) ? a : expm1f(a);
                v[i][2 * j2 + 1] = (b > 0.f) ? b : expm1f(b);
            }
        // write h1^T back into As
#pragma unroll
        for (int j = 0; j < 8; j++) {
            int c = c0 + j;
            float* base = As + c * 128 + (r0 ^ (((c >> 3) & 15) << 3));
            *(float4*)(base)     = make_float4(v[0][j], v[1][j], v[2][j], v[3][j]);
            *(float4*)(base + 4) = make_float4(v[4][j], v[5][j], v[6][j], v[7][j]);
        }
    }
    stage_W(Ws, W2, tid);
    BSYNC();

    // ===== GEMM 2: xf = h1@W2^T + b2 =====
    ZERO_ACC;
    gemm_acc(As, Ws, acc, r0, c0);
    BSYNC();
    {
        float bb[8];
#pragma unroll
        for (int j = 0; j < 8; j++) bb[j] = b2[c0 + j];
#pragma unroll
        for (int i = 0; i < 8; i++)
#pragma unroll
            for (int j2 = 0; j2 < 4; j2++) {
                float2 p = upk(acc[i * 4 + j2]);
                v[i][2 * j2]     = p.x + bb[2 * j2];
                v[i][2 * j2 + 1] = p.y + bb[2 * j2 + 1];
            }
#pragma unroll
        for (int j = 0; j < 8; j++) {
            int c = c0 + j;
            float* base = As + c * 128 + (r0 ^ (((c >> 3) & 15) << 3));
            *(float4*)(base)     = make_float4(v[0][j], v[1][j], v[2][j], v[3][j]);
            *(float4*)(base + 4) = make_float4(v[4][j], v[5][j], v[6][j], v[7][j]);
        }
    }

    // ===== r gate: r = sigmoid(xf@Wihr^T + mem@Whhr^T + b_ihr + b_hhr) =====
    stage_W(Ws, W_ih, tid);
    BSYNC();
    ZERO_ACC;
    gemm_acc(As, Ws, acc, r0, c0);
    BSYNC();
    stage_W(Ws, W_hh, tid);
    BSYNC();
    gemm_acc(Ms, Ws, acc, r0, c0);
    {
        float ba[8], bb[8];
#pragma unroll
        for (int j = 0; j < 8; j++) { ba[j] = b_ih[c0 + j]; bb[j] = b_hh[c0 + j]; }
#pragma unroll
        for (int i = 0; i < 8; i++)
#pragma unroll
            for (int j2 = 0; j2 < 4; j2++) {
                float2 p = upk(acc[i * 4 + j2]);
                hold[i][2 * j2]     = sigf(p.x + ba[2 * j2] + bb[2 * j2]);
                hold[i][2 * j2 + 1] = sigf(p.y + ba[2 * j2 + 1] + bb[2 * j2 + 1]);
            }
    }
    BSYNC();

    // ===== ghn: hold = r * (mem@Whhn^T + b_hhn) =====
    stage_W(Ws, W_hh + 2 * 16384, tid);
    BSYNC();
    ZERO_ACC;
    gemm_acc(Ms, Ws, acc, r0, c0);
    {
        float bb[8];
#pragma unroll
        for (int j = 0; j < 8; j++) bb[j] = b_hh[256 + c0 + j];
#pragma unroll
        for (int i = 0; i < 8; i++)
#pragma unroll
            for (int j2 = 0; j2 < 4; j2++) {
                float2 p = upk(acc[i * 4 + j2]);
                hold[i][2 * j2]     *= (p.x + bb[2 * j2]);
                hold[i][2 * j2 + 1] *= (p.y + bb[2 * j2 + 1]);
            }
    }
    BSYNC();

    // ===== i_n: hold = tanh(xf@Wihn^T + b_ihn + hold) =====
    stage_W(Ws, W_ih + 2 * 16384, tid);
    BSYNC();
    ZERO_ACC;
    gemm_acc(As, Ws, acc, r0, c0);
    {
        float bb[8];
#pragma unroll
        for (int j = 0; j < 8; j++) bb[j] = b_ih[256 + c0 + j];
#pragma unroll
        for (int i = 0; i < 8; i++)
#pragma unroll
            for (int j2 = 0; j2 < 4; j2++) {
                float2 p = upk(acc[i * 4 + j2]);
                hold[i][2 * j2]     = tanhf(p.x + bb[2 * j2] + hold[i][2 * j2]);
                hold[i][2 * j2 + 1] = tanhf(p.y + bb[2 * j2 + 1] + hold[i][2 * j2 + 1]);
            }
    }
    BSYNC();

    // ===== z gate + combine =====
    stage_W(Ws, W_ih + 16384, tid);
    BSYNC();
    ZERO_ACC;
    gemm_acc(As, Ws, acc, r0, c0);
    BSYNC();
    stage_W(Ws, W_hh + 16384, tid);
    BSYNC();
    gemm_acc(Ms, Ws, acc, r0, c0);
    {
        float ba[8], bb[8];
#pragma unroll
        for (int j = 0; j < 8; j++) { ba[j] = b_ih[128 + c0 + j]; bb[j] = b_hh[128 + c0 + j]; }
        // mem values for this thread's patch from Ms
        float mv[8][8];
#pragma unroll
        for (int j = 0; j < 8; j++) {
            int c = c0 + j;
            const float* base = Ms + c * 128 + (r0 ^ (((c >> 3) & 15) << 3));
            float4 lo = *(const float4*)(base);
            float4 hi = *(const float4*)(base + 4);
            mv[0][j] = lo.x; mv[1][j] = lo.y; mv[2][j] = lo.z; mv[3][j] = lo.w;
            mv[4][j] = hi.x; mv[5][j] = hi.y; mv[6][j] = hi.z; mv[7][j] = hi.w;
        }
#pragma unroll
        for (int i = 0; i < 8; i++) {
            float o[8];
#pragma unroll
            for (int j2 = 0; j2 < 4; j2++) {
                float2 p = upk(acc[i * 4 + j2]);
                float z0 = sigf(p.x + ba[2 * j2] + bb[2 * j2]);
                float z1 = sigf(p.y + ba[2 * j2 + 1] + bb[2 * j2 + 1]);
                o[2 * j2]     = (1.f - z0) * hold[i][2 * j2]     + z0 * mv[i][2 * j2];
                o[2 * j2 + 1] = (1.f - z1) * hold[i][2 * j2 + 1] + z1 * mv[i][2 * j2 + 1];
            }
            int rrow = (int)(rowbase) + r0 + i;
            float* orow = out + (long long)rrow * Dm + c0;
            float4 o_lo = make_float4(o[0], o[1], o[2], o[3]);
            float4 o_hi = make_float4(o[4], o[5], o[6], o[7]);
            *(float4*)(orow)     = o_lo;
            *(float4*)(orow + 4) = o_hi;
            // winner row: this CTA owns the scatter into new_history slot 2
            int gi = sIdx[r0 + i];
            if (__ldg(&g_winner[gi]) == rrow) {
                float* hrow = nh + ((long long)2 * NROWS + gi) * Dm + c0;
                *(float4*)(hrow)     = o_lo;
                *(float4*)(hrow + 4) = o_hi;
            }
        }
    }
}

// ---------------- launcher ----------------

extern "C" void kernel_launch(void* const* d_in, const int* in_sizes, int n_in,
                              void* d_out, int out_size) {
    (void)in_sizes; (void)n_in; (void)out_size;
    const float* x    = (const float*)d_in[0];
    const int*   idx  = (const int*)d_in[1];
    const float* hist = (const float*)d_in[2];
    const float* W1   = (const float*)d_in[3];
    const float* b1   = (const float*)d_in[4];
    const float* W2   = (const float*)d_in[5];
    const float* b2   = (const float*)d_in[6];
    const float* W_ih = (const float*)d_in[7];
    const float* b_ih = (const float*)d_in[8];
    const float* W_hh = (const float*)d_in[9];
    const float* b_hh = (const float*)d_in[10];

    float* out    = (float*)d_out;
    float* memout = out + (long long)BATCH * Dm;
    float* nh     = memout + (long long)BATCH * Dm;

    cudaFuncSetAttribute(k_compute, cudaFuncAttributeMaxDynamicSharedMemorySize, SMEM_BYTES);

    k_winit<<<(NROWS + 511) / 512, 512>>>();
    k_wscatter<<<(BATCH + 255) / 256, 256>>>(idx);
    k_compute<<<NCTA, 256 + NCOPYT, SMEM_BYTES>>>(x, idx, hist, W1, b1, W2, b2,
                                                  W_ih, b_ih, W_hh, b_hh,
                                                  out, memout, nh);
}

// round 6
// speedup vs baseline: 4.1475x; 4.1475x over previous
#include <cuda_runtime.h>
#include <math.h>

#define Dm      128
#define BATCH   65536
#define NROWS   500000
#define TSLOTS  3
#define SWW     132

#define AS_FLOATS   (128 * 128)
#define SMEM_FLOATS (AS_FLOATS * 2 + 128 * SWW)
#define SMEM_BYTES  (SMEM_FLOATS * 4 + 512)

__device__ int g_winner[NROWS];

// ---------------- helpers ----------------

// transposed activation layout: element (feature k, row r) at k*128 + (r XOR-swizzled)
__device__ __forceinline__ int aoff(int k, int r) {
    return k * 128 + (r ^ (((k >> 3) & 15) << 3));
}

__device__ __forceinline__ unsigned long long pk2(float v) {
    unsigned long long r;
    asm("mov.b64 %0, {%1, %1};" : "=l"(r) : "f"(v));
    return r;
}
__device__ __forceinline__ void ffma2(unsigned long long& d,
                                      unsigned long long a,
                                      unsigned long long b) {
    asm("fma.rn.f32x2 %0, %1, %2, %0;" : "+l"(d) : "l"(a), "l"(b));
}
__device__ __forceinline__ float2 upk(unsigned long long v) {
    float2 f;
    asm("mov.b64 {%0, %1}, %2;" : "=f"(f.x), "=f"(f.y) : "l"(v));
    return f;
}
__device__ __forceinline__ float sigf(float x) { return 1.0f / (1.0f + expf(-x)); }

// stage W tile: Ws[k][c] = Wg[c*128 + k]   (Wg row-major [out_c][in_k])
__device__ __forceinline__ void stage_W(float* __restrict__ Ws,
                                        const float* __restrict__ Wg, int tid) {
    const float4* W4 = (const float4*)Wg;
#pragma unroll
    for (int m = 0; m < 16; m++) {
        int f4 = tid + m * 256;      // float4 index over 4096
        int c  = f4 >> 5;            // 32 float4 per row of 128
        int kq = f4 & 31;
        float4 v = W4[f4];           // == Wg[c][4*kq .. 4*kq+3], coalesced
        int kk = kq * 4;
        Ws[(kk + 0) * SWW + c] = v.x;
        Ws[(kk + 1) * SWW + c] = v.y;
        Ws[(kk + 2) * SWW + c] = v.z;
        Ws[(kk + 3) * SWW + c] = v.w;
    }
}

// acc[r_i][c_pair] += A^T[k][r0+i] * Ws[k][c0+j]; acc packed as f32x2 col pairs
__device__ __forceinline__ void gemm_acc(const float* __restrict__ A,
                                         const float* __restrict__ Ws,
                                         unsigned long long acc[32],
                                         int r0, int c0) {
#pragma unroll 4
    for (int k = 0; k < 128; k++) {
        int sw = ((k >> 3) & 15) << 3;
        const float* abase = A + k * 128 + (r0 ^ sw);
        float4 a0 = *(const float4*)(abase);
        float4 a1 = *(const float4*)(abase + 4);
        const ulonglong2* wrow = (const ulonglong2*)(Ws + k * SWW + c0);
        ulonglong2 w01 = wrow[0];   // .x = cols(c0,c0+1) .y = cols(c0+2,c0+3)
        ulonglong2 w23 = wrow[1];
        unsigned long long ap[8];
        ap[0] = pk2(a0.x); ap[1] = pk2(a0.y); ap[2] = pk2(a0.z); ap[3] = pk2(a0.w);
        ap[4] = pk2(a1.x); ap[5] = pk2(a1.y); ap[6] = pk2(a1.z); ap[7] = pk2(a1.w);
#pragma unroll
        for (int i = 0; i < 8; i++) {
            ffma2(acc[i * 4 + 0], ap[i], w01.x);
            ffma2(acc[i * 4 + 1], ap[i], w01.y);
            ffma2(acc[i * 4 + 2], ap[i], w23.x);
            ffma2(acc[i * 4 + 3], ap[i], w23.y);
        }
    }
}

#define ZERO_ACC                                            \
    _Pragma("unroll") for (int zz = 0; zz < 32; zz++) acc[zz] = 0ULL;

// ---------------- winner kernels ----------------

__global__ void k_winit() {
    int i = blockIdx.x * blockDim.x + threadIdx.x;
    if (i < NROWS) g_winner[i] = -1;
}

__global__ void k_wscatter(const int* __restrict__ idx) {
    int b = blockIdx.x * blockDim.x + threadIdx.x;
    if (b < BATCH) atomicMax(&g_winner[idx[b]], b);
}

// ---------------- fused compute kernel (R3-proven shape) ----------------

__global__ void __launch_bounds__(256, 1) k_compute(
    const float* __restrict__ x, const int* __restrict__ idx,
    const float* __restrict__ hist,
    const float* __restrict__ W1, const float* __restrict__ b1,
    const float* __restrict__ W2, const float* __restrict__ b2,
    const float* __restrict__ W_ih, const float* __restrict__ b_ih,
    const float* __restrict__ W_hh, const float* __restrict__ b_hh,
    float* __restrict__ out, float* __restrict__ memout,
    float* __restrict__ nh)
{
    extern __shared__ float sm[];
    float* As = sm;                  // xf / activations, transposed [k][r]
    float* Ms = sm + AS_FLOATS;      // mem, transposed [k][r]
    float* Ws = sm + 2 * AS_FLOATS;  // weight tile [k][c], stride SWW
    int*   sIdx = (int*)(sm + SMEM_FLOATS);  // idx cache for this tile

    const int tid = threadIdx.x;
    const int tx  = tid & 15;
    const int ty  = tid >> 4;
    const int r0  = ty * 8;
    const int c0  = tx * 8;
    const long long rowbase = (long long)blockIdx.x * 128;

    // ---- load x tile and gather mem tile (transposed into smem), write mem out ----
    {
        int row  = tid >> 1;
        int half = tid & 1;
        const float4* xr = (const float4*)(x + (rowbase + row) * Dm) + half * 16;
        int gi = idx[rowbase + row];
        if (half == 0) sIdx[row] = gi;
        const float4* mr =
            (const float4*)(hist + ((long long)(TSLOTS - 1) * NROWS + gi) * Dm) + half * 16;
        float4* mo = (float4*)(memout + (rowbase + row) * Dm) + half * 16;
#pragma unroll
        for (int m = 0; m < 16; m++) {
            float4 vx = xr[m];
            float4 vm = mr[m];
            mo[m] = vm;
            int k = half * 64 + m * 4;
            As[aoff(k + 0, row)] = vx.x;
            As[aoff(k + 1, row)] = vx.y;
            As[aoff(k + 2, row)] = vx.z;
            As[aoff(k + 3, row)] = vx.w;
            Ms[aoff(k + 0, row)] = vm.x;
            Ms[aoff(k + 1, row)] = vm.y;
            Ms[aoff(k + 2, row)] = vm.z;
            Ms[aoff(k + 3, row)] = vm.w;
        }
    }

    unsigned long long acc[32];
    float hold[8][8];   // r -> r*ghn -> n
    float v[8][8];      // scratch

    // ===== GEMM 1: h1 = elu(x@W1^T + b1) =====
    stage_W(Ws, W1, tid);
    __syncthreads();
    ZERO_ACC;
    gemm_acc(As, Ws, acc, r0, c0);
    __syncthreads();   // all reads of As/Ws done
    {
        float bb[8];
#pragma unroll
        for (int j = 0; j < 8; j++) bb[j] = b1[c0 + j];
#pragma unroll
        for (int i = 0; i < 8; i++)
#pragma unroll
            for (int j2 = 0; j2 < 4; j2++) {
                float2 p = upk(acc[i * 4 + j2]);
                float a = p.x + bb[2 * j2];
                float b = p.y + bb[2 * j2 + 1];
                v[i][2 * j2]     = (a > 0.f) ? a : expm1f(a);
                v[i][2 * j2 + 1] = (b > 0.f) ? b : expm1f(b);
            }
        // write h1^T back into As
#pragma unroll
        for (int j = 0; j < 8; j++) {
            int c = c0 + j;
            float* base = As + c * 128 + (r0 ^ (((c >> 3) & 15) << 3));
            *(float4*)(base)     = make_float4(v[0][j], v[1][j], v[2][j], v[3][j]);
            *(float4*)(base + 4) = make_float4(v[4][j], v[5][j], v[6][j], v[7][j]);
        }
    }
    stage_W(Ws, W2, tid);
    __syncthreads();

    // ===== GEMM 2: xf = h1@W2^T + b2 =====
    ZERO_ACC;
    gemm_acc(As, Ws, acc, r0, c0);
    __syncthreads();
    {
        float bb[8];
#pragma unroll
        for (int j = 0; j < 8; j++) bb[j] = b2[c0 + j];
#pragma unroll
        for (int i = 0; i < 8; i++)
#pragma unroll
            for (int j2 = 0; j2 < 4; j2++) {
                float2 p = upk(acc[i * 4 + j2]);
                v[i][2 * j2]     = p.x + bb[2 * j2];
                v[i][2 * j2 + 1] = p.y + bb[2 * j2 + 1];
            }
#pragma unroll
        for (int j = 0; j < 8; j++) {
            int c = c0 + j;
            float* base = As + c * 128 + (r0 ^ (((c >> 3) & 15) << 3));
            *(float4*)(base)     = make_float4(v[0][j], v[1][j], v[2][j], v[3][j]);
            *(float4*)(base + 4) = make_float4(v[4][j], v[5][j], v[6][j], v[7][j]);
        }
    }

    // ===== r gate: r = sigmoid(xf@Wihr^T + mem@Whhr^T + b_ihr + b_hhr) =====
    stage_W(Ws, W_ih, tid);
    __syncthreads();
    ZERO_ACC;
    gemm_acc(As, Ws, acc, r0, c0);
    __syncthreads();
    stage_W(Ws, W_hh, tid);
    __syncthreads();
    gemm_acc(Ms, Ws, acc, r0, c0);
    {
        float ba[8], bb[8];
#pragma unroll
        for (int j = 0; j < 8; j++) { ba[j] = b_ih[c0 + j]; bb[j] = b_hh[c0 + j]; }
#pragma unroll
        for (int i = 0; i < 8; i++)
#pragma unroll
            for (int j2 = 0; j2 < 4; j2++) {
                float2 p = upk(acc[i * 4 + j2]);
                hold[i][2 * j2]     = sigf(p.x + ba[2 * j2] + bb[2 * j2]);
                hold[i][2 * j2 + 1] = sigf(p.y + ba[2 * j2 + 1] + bb[2 * j2 + 1]);
            }
    }
    __syncthreads();

    // ===== ghn: hold = r * (mem@Whhn^T + b_hhn) =====
    stage_W(Ws, W_hh + 2 * 16384, tid);
    __syncthreads();
    ZERO_ACC;
    gemm_acc(Ms, Ws, acc, r0, c0);
    {
        float bb[8];
#pragma unroll
        for (int j = 0; j < 8; j++) bb[j] = b_hh[256 + c0 + j];
#pragma unroll
        for (int i = 0; i < 8; i++)
#pragma unroll
            for (int j2 = 0; j2 < 4; j2++) {
                float2 p = upk(acc[i * 4 + j2]);
                hold[i][2 * j2]     *= (p.x + bb[2 * j2]);
                hold[i][2 * j2 + 1] *= (p.y + bb[2 * j2 + 1]);
            }
    }
    __syncthreads();

    // ===== i_n: hold = tanh(xf@Wihn^T + b_ihn + hold) =====
    stage_W(Ws, W_ih + 2 * 16384, tid);
    __syncthreads();
    ZERO_ACC;
    gemm_acc(As, Ws, acc, r0, c0);
    {
        float bb[8];
#pragma unroll
        for (int j = 0; j < 8; j++) bb[j] = b_ih[256 + c0 + j];
#pragma unroll
        for (int i = 0; i < 8; i++)
#pragma unroll
            for (int j2 = 0; j2 < 4; j2++) {
                float2 p = upk(acc[i * 4 + j2]);
                hold[i][2 * j2]     = tanhf(p.x + bb[2 * j2] + hold[i][2 * j2]);
                hold[i][2 * j2 + 1] = tanhf(p.y + bb[2 * j2 + 1] + hold[i][2 * j2 + 1]);
            }
    }
    __syncthreads();

    // ===== z gate + combine =====
    stage_W(Ws, W_ih + 16384, tid);
    __syncthreads();
    ZERO_ACC;
    gemm_acc(As, Ws, acc, r0, c0);
    __syncthreads();
    stage_W(Ws, W_hh + 16384, tid);
    __syncthreads();
    gemm_acc(Ms, Ws, acc, r0, c0);
    {
        float ba[8], bb[8];
#pragma unroll
        for (int j = 0; j < 8; j++) { ba[j] = b_ih[128 + c0 + j]; bb[j] = b_hh[128 + c0 + j]; }
        // mem values for this thread's patch from Ms
        float mv[8][8];
#pragma unroll
        for (int j = 0; j < 8; j++) {
            int c = c0 + j;
            const float* base = Ms + c * 128 + (r0 ^ (((c >> 3) & 15) << 3));
            float4 lo = *(const float4*)(base);
            float4 hi = *(const float4*)(base + 4);
            mv[0][j] = lo.x; mv[1][j] = lo.y; mv[2][j] = lo.z; mv[3][j] = lo.w;
            mv[4][j] = hi.x; mv[5][j] = hi.y; mv[6][j] = hi.z; mv[7][j] = hi.w;
        }
#pragma unroll
        for (int i = 0; i < 8; i++) {
            float o[8];
#pragma unroll
            for (int j2 = 0; j2 < 4; j2++) {
                float2 p = upk(acc[i * 4 + j2]);
                float z0 = sigf(p.x + ba[2 * j2] + bb[2 * j2]);
                float z1 = sigf(p.y + ba[2 * j2 + 1] + bb[2 * j2 + 1]);
                o[2 * j2]     = (1.f - z0) * hold[i][2 * j2]     + z0 * mv[i][2 * j2];
                o[2 * j2 + 1] = (1.f - z1) * hold[i][2 * j2 + 1] + z1 * mv[i][2 * j2 + 1];
            }
            int rrow = (int)(rowbase) + r0 + i;
            float* orow = out + (long long)rrow * Dm + c0;
            float4 o_lo = make_float4(o[0], o[1], o[2], o[3]);
            float4 o_hi = make_float4(o[4], o[5], o[6], o[7]);
            *(float4*)(orow)     = o_lo;
            *(float4*)(orow + 4) = o_hi;
            // winner row: this CTA owns the scatter into new_history slot 2
            int gi = sIdx[r0 + i];
            if (__ldg(&g_winner[gi]) == rrow) {
                float* hrow = nh + ((long long)2 * NROWS + gi) * Dm + c0;
                *(float4*)(hrow)     = o_lo;
                *(float4*)(hrow + 4) = o_hi;
            }
        }
    }
}

// ---------------- history copy (t=0,1 shift + t=2 non-winner) ----------------
// No dependency on `out` — runs concurrently with k_compute on a second stream.

__global__ void k_hist_copy(const float* __restrict__ hist,
                            float* __restrict__ nh)
{
    const long long PER_T = (long long)NROWS * (Dm / 4);
    int t = blockIdx.y;
    long long rem = (long long)blockIdx.x * blockDim.x + threadIdx.x;  // over N*D/4
    int i = (int)(rem >> 5);      // D/4 = 32 float4 per row
    int w = __ldg(&g_winner[i]);
    long long gid = (long long)t * PER_T + rem;
    if (t < TSLOTS - 1) {
        ((float4*)nh)[gid] =
            ((const float4*)hist)[gid + (w >= 0 ? PER_T : 0)];
    } else if (w < 0) {
        ((float4*)nh)[gid] = ((const float4*)hist)[gid];
    }
}

// ---------------- launcher ----------------

extern "C" void kernel_launch(void* const* d_in, const int* in_sizes, int n_in,
                              void* d_out, int out_size) {
    (void)in_sizes; (void)n_in; (void)out_size;
    const float* x    = (const float*)d_in[0];
    const int*   idx  = (const int*)d_in[1];
    const float* hist = (const float*)d_in[2];
    const float* W1   = (const float*)d_in[3];
    const float* b1   = (const float*)d_in[4];
    const float* W2   = (const float*)d_in[5];
    const float* b2   = (const float*)d_in[6];
    const float* W_ih = (const float*)d_in[7];
    const float* b_ih = (const float*)d_in[8];
    const float* W_hh = (const float*)d_in[9];
    const float* b_hh = (const float*)d_in[10];

    float* out    = (float*)d_out;
    float* memout = out + (long long)BATCH * Dm;
    float* nh     = memout + (long long)BATCH * Dm;

    // one-time infrastructure (no device memory): second stream + fork/join events
    static cudaStream_t s2 = 0;
    static cudaEvent_t  eFork = 0, eJoin = 0;
    if (!s2) {
        cudaStreamCreateWithFlags(&s2, cudaStreamNonBlocking);
        cudaEventCreateWithFlags(&eFork, cudaEventDisableTiming);
        cudaEventCreateWithFlags(&eJoin, cudaEventDisableTiming);
        cudaFuncSetAttribute(k_compute, cudaFuncAttributeMaxDynamicSharedMemorySize,
                             SMEM_BYTES);
    }

    k_winit<<<(NROWS + 511) / 512, 512>>>();
    k_wscatter<<<(BATCH + 255) / 256, 256>>>(idx);

    // fork: history copy runs on s2, concurrent with compute on the main stream
    cudaEventRecord(eFork, 0);
    cudaStreamWaitEvent(s2, eFork, 0);

    dim3 hg((unsigned)((long long)NROWS * (Dm / 4) / 256), TSLOTS);
    k_hist_copy<<<hg, 256, 0, s2>>>(hist, nh);

    k_compute<<<BATCH / 128, 256, SMEM_BYTES>>>(x, idx, hist, W1, b1, W2, b2,
                                                W_ih, b_ih, W_hh, b_hh,
                                                out, memout, nh);

    // join: main stream waits for the copy before kernel_launch's work is "done"
    cudaEventRecord(eJoin, s2);
    cudaStreamWaitEvent(0, eJoin, 0);
}

// round 8
// speedup vs baseline: 6.3826x; 1.5389x over previous
#include <cuda_runtime.h>
#include <cuda_bf16.h>
#include <math.h>
#include <stdint.h>

#define Dm      128
#define BATCH   65536
#define NROWS   500000
#define TSLOTS  3

#define TILE_BYTES 32768           // 128 rows x 256B (128 bf16)
#define OFF_XHI  0
#define OFF_XLO  (1 * TILE_BYTES)
#define OFF_MHI  (2 * TILE_BYTES)
#define OFF_MLO  (3 * TILE_BYTES)
#define OFF_WHI  (4 * TILE_BYTES)
#define OFF_WLO  (5 * TILE_BYTES)
#define OFF_IDX  (6 * TILE_BYTES)
#define SMEM_REQ (6 * TILE_BYTES + 512)

__device__ int g_winner[NROWS];

// ---------------- low-level helpers ----------------

__device__ __forceinline__ uint32_t smem_u32(const void* p) {
    uint32_t a;
    asm("{ .reg .u64 t; cvta.to.shared.u64 t, %1; cvt.u32.u64 %0, t; }" : "=r"(a) : "l"(p));
    return a;
}

// swizzled byte offset of 16B chunk kb (0..15) in row r (0..127)
__device__ __forceinline__ uint32_t toff(int r, int kb) {
    return (uint32_t)r * 256u + (uint32_t)(((kb ^ (r & 7)) & 15) << 4);
}

__device__ __forceinline__ void ldm4(unsigned* d, uint32_t a) {
    asm volatile("ldmatrix.sync.aligned.m8n8.x4.shared.b16 {%0,%1,%2,%3}, [%4];"
        : "=r"(d[0]), "=r"(d[1]), "=r"(d[2]), "=r"(d[3]) : "r"(a));
}

__device__ __forceinline__ void mma16816(float* d, const unsigned* a,
                                         unsigned b0, unsigned b1) {
    asm volatile("mma.sync.aligned.m16n8k16.row.col.f32.bf16.bf16.f32 "
        "{%0,%1,%2,%3}, {%4,%5,%6,%7}, {%8,%9}, {%0,%1,%2,%3};"
        : "+f"(d[0]), "+f"(d[1]), "+f"(d[2]), "+f"(d[3])
        : "r"(a[0]), "r"(a[1]), "r"(a[2]), "r"(a[3]), "r"(b0), "r"(b1));
}

__device__ __forceinline__ float sigf(float x) { return 1.0f / (1.0f + expf(-x)); }

// pack 8 fp32 -> 16B hi + 16B lo bf16 and store at (row, kb)
__device__ __forceinline__ void pack_store(char* smx, uint32_t offHi, uint32_t offLo,
                                           int row, int kb, const float* w8) {
    uint4 hi, lo;
    unsigned* hp = (unsigned*)&hi;
    unsigned* lp = (unsigned*)&lo;
#pragma unroll
    for (int q = 0; q < 4; q++) {
        float a = w8[2 * q], b = w8[2 * q + 1];
        __nv_bfloat16 ah = __float2bfloat16(a), bh = __float2bfloat16(b);
        __nv_bfloat16 al = __float2bfloat16(a - __bfloat162float(ah));
        __nv_bfloat16 bl = __float2bfloat16(b - __bfloat162float(bh));
        hp[q] = ((unsigned)__bfloat16_as_ushort(bh) << 16) | (unsigned)__bfloat16_as_ushort(ah);
        lp[q] = ((unsigned)__bfloat16_as_ushort(bl) << 16) | (unsigned)__bfloat16_as_ushort(al);
    }
    uint32_t a = toff(row, kb);
    *(uint4*)(smx + offHi + a) = hi;
    *(uint4*)(smx + offLo + a) = lo;
}

// stage 128x128 fp32 row-major global matrix into hi/lo bf16 tiles
__device__ __forceinline__ void stage_mat(const float* __restrict__ G, char* smx,
                                          uint32_t offHi, uint32_t offLo, int tid) {
    int row = tid >> 1, half = tid & 1;
    const float4* g4 = (const float4*)(G + (size_t)row * 128 + half * 64);
#pragma unroll
    for (int j = 0; j < 8; j++) {
        float4 qa = g4[2 * j], qb = g4[2 * j + 1];
        float w8[8] = { qa.x, qa.y, qa.z, qa.w, qb.x, qb.y, qb.z, qb.w };
        pack_store(smx, offHi, offLo, row, half * 8 + j, w8);
    }
}

// store fp32 pair (cols c, c+1; c even) of row r into hi/lo tiles
__device__ __forceinline__ void st_pair(char* smx, uint32_t offHi, uint32_t offLo,
                                        int r, int c, float v0, float v1) {
    uint32_t a = toff(r, c >> 3) + (uint32_t)(c & 7) * 2u;
    __nv_bfloat16 h0 = __float2bfloat16(v0), h1 = __float2bfloat16(v1);
    __nv_bfloat16 l0 = __float2bfloat16(v0 - __bfloat162float(h0));
    __nv_bfloat16 l1 = __float2bfloat16(v1 - __bfloat162float(h1));
    *(unsigned*)(smx + offHi + a) =
        ((unsigned)__bfloat16_as_ushort(h1) << 16) | (unsigned)__bfloat16_as_ushort(h0);
    *(unsigned*)(smx + offLo + a) =
        ((unsigned)__bfloat16_as_ushort(l1) << 16) | (unsigned)__bfloat16_as_ushort(l0);
}

// read fp32 pair (hi+lo) at (r, c)
__device__ __forceinline__ float2 ld_pair(const char* smx, uint32_t offHi, uint32_t offLo,
                                          int r, int c) {
    uint32_t a = toff(r, c >> 3) + (uint32_t)(c & 7) * 2u;
    unsigned h = *(const unsigned*)(smx + offHi + a);
    unsigned l = *(const unsigned*)(smx + offLo + a);
    float2 v;
    v.x = __bfloat162float(__ushort_as_bfloat16((unsigned short)(h & 0xffff))) +
          __bfloat162float(__ushort_as_bfloat16((unsigned short)(l & 0xffff)));
    v.y = __bfloat162float(__ushort_as_bfloat16((unsigned short)(h >> 16))) +
          __bfloat162float(__ushort_as_bfloat16((unsigned short)(l >> 16)));
    return v;
}

// 3-pass bf16-split GEMM: acc += A(128x128) @ W(128x128)^T, this warp's 32x64 patch
__device__ __forceinline__ void gemm3(uint32_t sb, uint32_t offAhi, uint32_t offAlo,
                                      float acc[2][8][4], int m0, int n0, int lane) {
    const int rA  = m0 + (lane & 7) + ((lane >> 3) & 1) * 8;
    const int kA  = lane >> 4;            // A kb low bit
    const int rBb = (lane & 7) + (lane >> 4) * 8;
    const int kB  = (lane >> 3) & 1;      // B kb low bit
    const int swA = rA & 7;
#pragma unroll 1
    for (int p = 0; p < 3; p++) {
        uint32_t tA = sb + ((p == 2) ? offAlo : offAhi);
        uint32_t tW = sb + (uint32_t)((p == 1) ? OFF_WLO : OFF_WHI);
        uint32_t a0base = tA + (uint32_t)rA * 256u;
        uint32_t a1base = tA + (uint32_t)(rA + 16) * 256u;
#pragma unroll
        for (int s = 0; s < 8; s++) {
            int kb = 2 * s + kA;
            unsigned a0[4], a1[4];
            ldm4(a0, a0base + (uint32_t)((kb ^ swA) << 4));
            ldm4(a1, a1base + (uint32_t)((kb ^ swA) << 4));
            int kbB = 2 * s + kB;
#pragma unroll
            for (int q = 0; q < 4; q++) {
                int rB = n0 + q * 16 + rBb;
                unsigned b[4];
                ldm4(b, tW + (uint32_t)rB * 256u + (uint32_t)(((kbB ^ (rB & 7)) & 15) << 4));
                mma16816(acc[0][2 * q + 0], a0, b[0], b[1]);
                mma16816(acc[0][2 * q + 1], a0, b[2], b[3]);
                mma16816(acc[1][2 * q + 0], a1, b[0], b[1]);
                mma16816(acc[1][2 * q + 1], a1, b[2], b[3]);
            }
        }
    }
}

#define ZACC do {                                                         \
    _Pragma("unroll") for (int z1 = 0; z1 < 2; z1++)                      \
    _Pragma("unroll") for (int z2 = 0; z2 < 8; z2++)                      \
    _Pragma("unroll") for (int z3 = 0; z3 < 4; z3++) acc[z1][z2][z3] = 0.f; \
} while (0)

// ---------------- winner kernels ----------------

__global__ void k_winit() {
    int i = blockIdx.x * blockDim.x + threadIdx.x;
    if (i < NROWS) g_winner[i] = -1;
}
__global__ void k_wscatter(const int* __restrict__ idx) {
    int b = blockIdx.x * blockDim.x + threadIdx.x;
    if (b < BATCH) atomicMax(&g_winner[idx[b]], b);
}

// ---------------- tensor-core (mma.sync) compute kernel ----------------

__global__ void __launch_bounds__(256, 1) k_compute(
    const float* __restrict__ x, const int* __restrict__ idx,
    const float* __restrict__ hist,
    const float* __restrict__ W1, const float* __restrict__ b1,
    const float* __restrict__ W2, const float* __restrict__ b2,
    const float* __restrict__ W_ih, const float* __restrict__ b_ih,
    const float* __restrict__ W_hh, const float* __restrict__ b_hh,
    float* __restrict__ out, float* __restrict__ memout,
    float* __restrict__ nh)
{
    extern __shared__ char smx[];
    const uint32_t sb = smem_u32(smx);
    int* sIdx = (int*)(smx + OFF_IDX);

    const int tid  = threadIdx.x;
    const int wid  = tid >> 5, lane = tid & 31;
    const int m0   = (wid & 3) * 32;
    const int n0   = (wid >> 2) * 64;
    const int rBase = lane >> 2;
    const int cBase = (lane & 3) * 2;
    const long long rowbase = (long long)blockIdx.x * 128;

    // ---- stage X ----
    stage_mat(x + rowbase * Dm, smx, OFF_XHI, OFF_XLO, tid);

    // ---- gather + stage M (and write memout, cache idx) ----
    {
        int row = tid >> 1, half = tid & 1;
        int gi = idx[rowbase + row];
        if (half == 0) sIdx[row] = gi;
        const float4* g4 = (const float4*)(hist + (2LL * NROWS + gi) * Dm + half * 64);
        float4* mo = (float4*)(memout + (rowbase + row) * Dm + half * 64);
#pragma unroll
        for (int j = 0; j < 8; j++) {
            float4 qa = g4[2 * j], qb = g4[2 * j + 1];
            mo[2 * j] = qa; mo[2 * j + 1] = qb;
            float w8[8] = { qa.x, qa.y, qa.z, qa.w, qb.x, qb.y, qb.z, qb.w };
            pack_store(smx, OFF_MHI, OFF_MLO, row, half * 8 + j, w8);
        }
    }

    stage_mat(W1, smx, OFF_WHI, OFF_WLO, tid);
    __syncthreads();

    float acc[2][8][4];
    float hold[2][8][4];

    // ===== P1: h1 = elu(x @ W1^T + b1) =====
    ZACC;
    gemm3(sb, OFF_XHI, OFF_XLO, acc, m0, n0, lane);
    __syncthreads();
#pragma unroll
    for (int nt = 0; nt < 8; nt++) {
        int c = n0 + nt * 8 + cBase;
        float2 bv = *(const float2*)(b1 + c);
#pragma unroll
        for (int mt = 0; mt < 2; mt++)
#pragma unroll
            for (int eh = 0; eh < 2; eh++) {
                int r = m0 + mt * 16 + rBase + eh * 8;
                float v0 = acc[mt][nt][eh * 2 + 0] + bv.x;
                float v1 = acc[mt][nt][eh * 2 + 1] + bv.y;
                v0 = (v0 > 0.f) ? v0 : expm1f(v0);
                v1 = (v1 > 0.f) ? v1 : expm1f(v1);
                st_pair(smx, OFF_XHI, OFF_XLO, r, c, v0, v1);
            }
    }
    stage_mat(W2, smx, OFF_WHI, OFF_WLO, tid);
    __syncthreads();

    // ===== P2: xf = h1 @ W2^T + b2 =====
    ZACC;
    gemm3(sb, OFF_XHI, OFF_XLO, acc, m0, n0, lane);
    __syncthreads();
#pragma unroll
    for (int nt = 0; nt < 8; nt++) {
        int c = n0 + nt * 8 + cBase;
        float2 bv = *(const float2*)(b2 + c);
#pragma unroll
        for (int mt = 0; mt < 2; mt++)
#pragma unroll
            for (int eh = 0; eh < 2; eh++) {
                int r = m0 + mt * 16 + rBase + eh * 8;
                st_pair(smx, OFF_XHI, OFF_XLO, r, c,
                        acc[mt][nt][eh * 2 + 0] + bv.x,
                        acc[mt][nt][eh * 2 + 1] + bv.y);
            }
    }
    stage_mat(W_ih, smx, OFF_WHI, OFF_WLO, tid);      // r gate, ih
    __syncthreads();

    // ===== P3: r = sigmoid(xf@Wihr^T + mem@Whhr^T + b_ihr + b_hhr) =====
    ZACC;
    gemm3(sb, OFF_XHI, OFF_XLO, acc, m0, n0, lane);
    __syncthreads();
    stage_mat(W_hh, smx, OFF_WHI, OFF_WLO, tid);      // r gate, hh
    __syncthreads();
    gemm3(sb, OFF_MHI, OFF_MLO, acc, m0, n0, lane);   // accumulate
    __syncthreads();
#pragma unroll
    for (int nt = 0; nt < 8; nt++) {
        int c = n0 + nt * 8 + cBase;
        float2 ba = *(const float2*)(b_ih + c);
        float2 bh = *(const float2*)(b_hh + c);
#pragma unroll
        for (int mt = 0; mt < 2; mt++)
#pragma unroll
            for (int e = 0; e < 4; e++) {
                float bb = (e & 1) ? (ba.y + bh.y) : (ba.x + bh.x);
                hold[mt][nt][e] = sigf(acc[mt][nt][e] + bb);
            }
    }
    stage_mat(W_hh + 2 * 16384, smx, OFF_WHI, OFF_WLO, tid);   // n gate, hh
    __syncthreads();

    // ===== P4: hold = r * (mem@Whhn^T + b_hhn) =====
    ZACC;
    gemm3(sb, OFF_MHI, OFF_MLO, acc, m0, n0, lane);
    __syncthreads();
#pragma unroll
    for (int nt = 0; nt < 8; nt++) {
        int c = n0 + nt * 8 + cBase;
        float2 bv = *(const float2*)(b_hh + 256 + c);
#pragma unroll
        for (int mt = 0; mt < 2; mt++)
#pragma unroll
            for (int e = 0; e < 4; e++) {
                float bb = (e & 1) ? bv.y : bv.x;
                hold[mt][nt][e] *= (acc[mt][nt][e] + bb);
            }
    }
    stage_mat(W_ih + 2 * 16384, smx, OFF_WHI, OFF_WLO, tid);   // n gate, ih
    __syncthreads();

    // ===== P5: hold = tanh(xf@Wihn^T + b_ihn + hold) =====
    ZACC;
    gemm3(sb, OFF_XHI, OFF_XLO, acc, m0, n0, lane);
    __syncthreads();
#pragma unroll
    for (int nt = 0; nt < 8; nt++) {
        int c = n0 + nt * 8 + cBase;
        float2 bv = *(const float2*)(b_ih + 256 + c);
#pragma unroll
        for (int mt = 0; mt < 2; mt++)
#pragma unroll
            for (int e = 0; e < 4; e++) {
                float bb = (e & 1) ? bv.y : bv.x;
                hold[mt][nt][e] = tanhf(acc[mt][nt][e] + bb + hold[mt][nt][e]);
            }
    }
    stage_mat(W_ih + 16384, smx, OFF_WHI, OFF_WLO, tid);       // z gate, ih
    __syncthreads();

    // ===== P6: z gate + combine =====
    ZACC;
    gemm3(sb, OFF_XHI, OFF_XLO, acc, m0, n0, lane);
    __syncthreads();
    stage_mat(W_hh + 16384, smx, OFF_WHI, OFF_WLO, tid);       // z gate, hh
    __syncthreads();
    gemm3(sb, OFF_MHI, OFF_MLO, acc, m0, n0, lane);
    // no smem writes after this point; no sync needed before epilogue reads of tM
#pragma unroll
    for (int mt = 0; mt < 2; mt++)
#pragma unroll
        for (int eh = 0; eh < 2; eh++) {
            int r = m0 + mt * 16 + rBase + eh * 8;
            int grow = (int)rowbase + r;
            int gi = sIdx[r];
            bool win = (__ldg(&g_winner[gi]) == grow);
            float* orow = out + (long long)grow * Dm;
            float* hrow = nh + (2LL * NROWS + gi) * Dm;
#pragma unroll
            for (int nt = 0; nt < 8; nt++) {
                int c = n0 + nt * 8 + cBase;
                float2 ba = *(const float2*)(b_ih + 128 + c);
                float2 bh = *(const float2*)(b_hh + 128 + c);
                float2 mv = ld_pair(smx, OFF_MHI, OFF_MLO, r, c);
                float z0 = sigf(acc[mt][nt][eh * 2 + 0] + ba.x + bh.x);
                float z1 = sigf(acc[mt][nt][eh * 2 + 1] + ba.y + bh.y);
                float2 o;
                o.x = (1.f - z0) * hold[mt][nt][eh * 2 + 0] + z0 * mv.x;
                o.y = (1.f - z1) * hold[mt][nt][eh * 2 + 1] + z1 * mv.y;
                *(float2*)(orow + c) = o;
                if (win) *(float2*)(hrow + c) = o;
            }
        }
}

// ---------------- history copy (t=0,1 shift + t=2 non-winner) ----------------

__global__ void k_hist_copy(const float* __restrict__ hist,
                            float* __restrict__ nh)
{
    const long long PER_T = (long long)NROWS * (Dm / 4);
    int t = blockIdx.y;
    long long rem = (long long)blockIdx.x * blockDim.x + threadIdx.x;
    int i = (int)(rem >> 5);
    int w = __ldg(&g_winner[i]);
    long long gid = (long long)t * PER_T + rem;
    if (t < TSLOTS - 1) {
        ((float4*)nh)[gid] = ((const float4*)hist)[gid + (w >= 0 ? PER_T : 0)];
    } else if (w < 0) {
        ((float4*)nh)[gid] = ((const float4*)hist)[gid];
    }
}

// ---------------- launcher ----------------

extern "C" void kernel_launch(void* const* d_in, const int* in_sizes, int n_in,
                              void* d_out, int out_size) {
    (void)in_sizes; (void)n_in; (void)out_size;
    const float* x    = (const float*)d_in[0];
    const int*   idx  = (const int*)d_in[1];
    const float* hist = (const float*)d_in[2];
    const float* W1   = (const float*)d_in[3];
    const float* b1   = (const float*)d_in[4];
    const float* W2   = (const float*)d_in[5];
    const float* b2   = (const float*)d_in[6];
    const float* W_ih = (const float*)d_in[7];
    const float* b_ih = (const float*)d_in[8];
    const float* W_hh = (const float*)d_in[9];
    const float* b_hh = (const float*)d_in[10];

    float* out    = (float*)d_out;
    float* memout = out + (long long)BATCH * Dm;
    float* nh     = memout + (long long)BATCH * Dm;

    static cudaStream_t s2 = 0;
    static cudaEvent_t  eFork = 0, eJoin = 0;
    if (!s2) {
        cudaStreamCreateWithFlags(&s2, cudaStreamNonBlocking);
        cudaEventCreateWithFlags(&eFork, cudaEventDisableTiming);
        cudaEventCreateWithFlags(&eJoin, cudaEventDisableTiming);
        cudaFuncSetAttribute(k_compute, cudaFuncAttributeMaxDynamicSharedMemorySize,
                             SMEM_REQ);
    }

    k_winit<<<(NROWS + 511) / 512, 512>>>();
    k_wscatter<<<(BATCH + 255) / 256, 256>>>(idx);

    cudaEventRecord(eFork, 0);
    cudaStreamWaitEvent(s2, eFork, 0);

    // compute first so its CTAs claim SMs; copy backfills on s2
    k_compute<<<BATCH / 128, 256, SMEM_REQ>>>(x, idx, hist, W1, b1, W2, b2,
                                              W_ih, b_ih, W_hh, b_hh,
                                              out, memout, nh);
    dim3 hg((unsigned)((long long)NROWS * (Dm / 4) / 256), TSLOTS);
    k_hist_copy<<<hg, 256, 0, s2>>>(hist, nh);

    cudaEventRecord(eJoin, s2);
    cudaStreamWaitEvent(0, eJoin, 0);
}